// round 3
// baseline (speedup 1.0000x reference)
#include <cuda_runtime.h>
#include <cuda_fp16.h>
#include <cstdint>
#include <cstddef>

// ---------------- problem constants ----------------
#define LI_B 32
#define LI_S 256
#define LI_H 768
#define LI_BS (LI_B * LI_S)   // 8192

// main kernel tiling: CTA tile 128(m) x 256(n), 512 threads (16 warps 4x4),
// warp tile 32(m) x 64(n), K chunks of 64, 3-stage cp.async ring.
#define NKC 12                 // 768 / 64
#define STG_A 16384            // 128 rows x 128 B
#define STG_B 32768            // 256 rows x 128 B
#define STG_BYTES (STG_A + STG_B)   // 49152

// smem layout (dynamic)
#define OFF_DK   0             // 256 f32: scale * exp(-alpha*d)
#define OFF_KM   1024          // 256 f32
#define OFF_QM   2048          // 128 f32
#define OFF_RED  3072          // 4 wn x 128 rows x 2 f32 = 4096 B
#define OFF_RED2 7168          // 4 f32
#define OFF_STG  8192
#define SMEM_BYTES (OFF_STG + 3 * STG_BYTES)   // 155648

#define SWZ(c8, r) ((((c8) ^ ((r) & 7)) << 4))

// normalized fp16 copies of Q and K
__device__ __align__(128) __half g_qh[LI_BS * LI_H];
__device__ __align__(128) __half g_kh[LI_BS * LI_H];
__device__ float g_qmsum[LI_B];

// ---------------- helpers ----------------
__device__ __forceinline__ uint32_t smem_u32(const void* p) {
    uint32_t a;
    asm("{ .reg .u64 t; cvta.to.shared.u64 t, %1; cvt.u32.u64 %0, t; }"
        : "=r"(a) : "l"(p));
    return a;
}

__device__ __forceinline__ void ldsm_x4(uint32_t& r0, uint32_t& r1,
                                        uint32_t& r2, uint32_t& r3, uint32_t addr) {
    asm volatile("ldmatrix.sync.aligned.m8n8.x4.shared.b16 {%0,%1,%2,%3}, [%4];"
                 : "=r"(r0), "=r"(r1), "=r"(r2), "=r"(r3) : "r"(addr));
}

__device__ __forceinline__ void mma16816(float& c0, float& c1, float& c2, float& c3,
                                         uint32_t a0, uint32_t a1, uint32_t a2, uint32_t a3,
                                         uint32_t b0, uint32_t b1) {
    asm volatile(
        "mma.sync.aligned.m16n8k16.row.col.f32.f16.f16.f32 "
        "{%0,%1,%2,%3}, {%4,%5,%6,%7}, {%8,%9}, {%0,%1,%2,%3};"
        : "+f"(c0), "+f"(c1), "+f"(c2), "+f"(c3)
        : "r"(a0), "r"(a1), "r"(a2), "r"(a3), "r"(b0), "r"(b1));
}

__device__ __forceinline__ void cpa16(uint32_t dst, const void* src) {
    asm volatile("cp.async.cg.shared.global [%0], [%1], 16;"
                 :: "r"(dst), "l"(__cvta_generic_to_global(src)));
}

// ---------------- kernel 1: normalize rows to fp16 ----------------
__global__ __launch_bounds__(256) void li_norm(const float* __restrict__ q,
                                               const float* __restrict__ k) {
    int row = blockIdx.x;
    bool isq = row < LI_BS;
    int r = isq ? row : row - LI_BS;
    const float* src = (isq ? q : k) + (size_t)r * LI_H;
    __half* dh = (isq ? g_qh : g_kh) + (size_t)r * LI_H;
    int t = threadIdx.x;

    float x0 = src[t], x1 = src[t + 256], x2 = src[t + 512];
    float ss = x0 * x0 + x1 * x1 + x2 * x2;
    #pragma unroll
    for (int o = 16; o; o >>= 1) ss += __shfl_xor_sync(0xFFFFFFFFu, ss, o);

    __shared__ float red[8];
    if ((t & 31) == 0) red[t >> 5] = ss;
    __syncthreads();
    float tot = 0.f;
    #pragma unroll
    for (int w = 0; w < 8; w++) tot += red[w];
    float inv = 1.f / fmaxf(sqrtf(tot), 1e-12f);

    dh[t]       = __float2half_rn(x0 * inv);
    dh[t + 256] = __float2half_rn(x1 * inv);
    dh[t + 512] = __float2half_rn(x2 * inv);
}

// ---------------- kernel 2: qmask row sums + zero output ----------------
__global__ __launch_bounds__(256) void li_prep(const float* __restrict__ qmask,
                                               float* __restrict__ out) {
    int i = blockIdx.x, t = threadIdx.x;
    float v = qmask[i * 256 + t];
    #pragma unroll
    for (int o = 16; o; o >>= 1) v += __shfl_xor_sync(0xFFFFFFFFu, v, o);
    __shared__ float red[8];
    if ((t & 31) == 0) red[t >> 5] = v;
    __syncthreads();
    if (t == 0) {
        float s = 0.f;
        #pragma unroll
        for (int w = 0; w < 8; w++) s += red[w];
        g_qmsum[i] = fmaxf(s, 1.f);
    }
    if (t < 32) out[i * 32 + t] = 0.f;
}

// ---------------- stage loader ----------------
__device__ __forceinline__ void load_stage(uint32_t stg, int kc, int qbase, int jbase,
                                           int tid) {
    int col0 = kc * 64;
    #pragma unroll
    for (int l = 0; l < 6; l++) {
        int idx = l * 512 + tid;
        if (idx < 1024) {
            int r = idx >> 3, c8 = idx & 7;
            cpa16(stg + r * 128 + SWZ(c8, r),
                  g_qh + (size_t)(qbase + r) * LI_H + col0 + c8 * 8);
        } else {
            int ib = idx - 1024;
            int r = ib >> 3, c8 = ib & 7;
            cpa16(stg + STG_A + r * 128 + SWZ(c8, r),
                  g_kh + (size_t)(jbase + r) * LI_H + col0 + c8 * 8);
        }
    }
}

// ---------------- kernel 3: fused GEMM + decay-softmax + reduce ----------------
__global__ __launch_bounds__(512, 1) void li_main(
    const float* __restrict__ qmask, const float* __restrict__ kmask,
    const float* __restrict__ p_alpha, const float* __restrict__ p_lscale,
    float* __restrict__ out) {
    extern __shared__ char smem[];
    const uint32_t sb = smem_u32(smem);
    const int tid = threadIdx.x, wid = tid >> 5, lane = tid & 31;
    const int wm = wid & 3, wn = wid >> 2;     // warp grid 4(m) x 4(n)
    const int im = blockIdx.x;                  // 0..63
    const int i = im >> 1, mhalf = im & 1;
    const int j = blockIdx.y;                   // 0..31
    const int qbase = i * 256 + mhalf * 128;
    const int jbase = j * 256;

    float* dkS = (float*)(smem + OFF_DK);
    float* kmS = (float*)(smem + OFF_KM);
    float* qmS = (float*)(smem + OFF_QM);
    float* redS = (float*)(smem + OFF_RED);
    float* red2 = (float*)(smem + OFF_RED2);

    // tables
    {
        float araw = p_alpha[0];
        float alpha = fmaxf(araw, 0.f) + log1pf(__expf(-fabsf(araw)));
        float scale = __expf(p_lscale[0]);
        if (tid < 256) {
            dkS[tid] = scale * __expf(-alpha * (float)tid);
            kmS[tid] = kmask[jbase + tid];
        }
        if (tid >= 256 && tid < 384) qmS[tid - 256] = qmask[qbase + (tid - 256)];
    }

    const uint32_t stg0 = sb + OFF_STG;

    // prologue
    #pragma unroll
    for (int s = 0; s < 3; s++) {
        load_stage(stg0 + s * STG_BYTES, s, qbase, jbase, tid);
        asm volatile("cp.async.commit_group;" ::: "memory");
    }

    float acc[2][8][4];
    #pragma unroll
    for (int mt = 0; mt < 2; mt++)
        #pragma unroll
        for (int nt = 0; nt < 8; nt++)
            #pragma unroll
            for (int v = 0; v < 4; v++) acc[mt][nt][v] = 0.f;

    // mainloop
    for (int kc = 0; kc < NKC; kc++) {
        uint32_t stg = stg0 + (kc % 3) * STG_BYTES;
        asm volatile("cp.async.wait_group 2;" ::: "memory");
        __syncthreads();

        uint32_t sA = stg;
        uint32_t sB = stg + STG_A;
        #pragma unroll
        for (int ks = 0; ks < 4; ks++) {
            uint32_t a[2][4];
            #pragma unroll
            for (int mt = 0; mt < 2; mt++) {
                int r = wm * 32 + mt * 16 + (lane & 15);
                int c8 = ks * 2 + (lane >> 4);
                ldsm_x4(a[mt][0], a[mt][1], a[mt][2], a[mt][3],
                        sA + r * 128 + SWZ(c8, r));
            }
            uint32_t b[8][2];
            #pragma unroll
            for (int p = 0; p < 4; p++) {
                int r = wn * 64 + p * 16 + (lane & 15);
                int c8 = ks * 2 + (lane >> 4);
                uint32_t r0, r1, r2, r3;
                ldsm_x4(r0, r1, r2, r3, sB + r * 128 + SWZ(c8, r));
                b[2 * p][0] = r0;     b[2 * p][1] = r2;
                b[2 * p + 1][0] = r1; b[2 * p + 1][1] = r3;
            }
            #pragma unroll
            for (int mt = 0; mt < 2; mt++)
                #pragma unroll
                for (int nt = 0; nt < 8; nt++)
                    mma16816(acc[mt][nt][0], acc[mt][nt][1],
                             acc[mt][nt][2], acc[mt][nt][3],
                             a[mt][0], a[mt][1], a[mt][2], a[mt][3],
                             b[nt][0], b[nt][1]);
        }

        __syncthreads();
        if (kc + 3 < NKC) load_stage(stg, kc + 3, qbase, jbase, tid);
        asm volatile("cp.async.commit_group;" ::: "memory");
    }
    asm volatile("cp.async.wait_group 0;" ::: "memory");

    // ---------------- epilogue ----------------
    // each warp: rows [wm*32, +32), cols [wn*64, +64); per-row partial sums.
    #pragma unroll
    for (int mt = 0; mt < 2; mt++) {
        int rA = wm * 32 + mt * 16 + (lane >> 2);
        int rB = rA + 8;
        int sA_g = mhalf * 128 + rA;
        int sB_g = sA_g + 8;
        float eA = 0.f, seA = 0.f, eB = 0.f, seB = 0.f;
        #pragma unroll
        for (int nt = 0; nt < 8; nt++) {
            int t0 = wn * 64 + nt * 8 + (lane & 3) * 2;
            int t1 = t0 + 1;
            float km0 = kmS[t0], km1 = kmS[t1];
            float s00 = acc[mt][nt][0], s01 = acc[mt][nt][1];
            float s10 = acc[mt][nt][2], s11 = acc[mt][nt][3];
            int dA0 = abs(sA_g - t0), dA1 = abs(sA_g - t1);
            int dB0 = abs(sB_g - t0), dB1 = abs(sB_g - t1);
            float e;
            e = (km0 > 0.f) ? __expf(s00 * dkS[dA0]) : 0.f; eA += e; seA += e * s00;
            e = (km1 > 0.f) ? __expf(s01 * dkS[dA1]) : 0.f; eA += e; seA += e * s01;
            e = (km0 > 0.f) ? __expf(s10 * dkS[dB0]) : 0.f; eB += e; seB += e * s10;
            e = (km1 > 0.f) ? __expf(s11 * dkS[dB1]) : 0.f; eB += e; seB += e * s11;
        }
        // reduce over the 4 lanes sharing each row (lane&3 varies)
        #pragma unroll
        for (int o = 1; o <= 2; o <<= 1) {
            eA  += __shfl_xor_sync(0xFFFFFFFFu, eA, o);
            seA += __shfl_xor_sync(0xFFFFFFFFu, seA, o);
            eB  += __shfl_xor_sync(0xFFFFFFFFu, eB, o);
            seB += __shfl_xor_sync(0xFFFFFFFFu, seB, o);
        }
        if ((lane & 3) == 0) {
            redS[(wn * 128 + rA) * 2]     = eA;
            redS[(wn * 128 + rA) * 2 + 1] = seA;
            redS[(wn * 128 + rB) * 2]     = eB;
            redS[(wn * 128 + rB) * 2 + 1] = seB;
        }
    }
    __syncthreads();

    float part = 0.f;
    if (tid < 128) {
        int m = tid;
        float se = 0.f, sse = 0.f;
        #pragma unroll
        for (int w = 0; w < 4; w++) {
            se  += redS[(w * 128 + m) * 2];
            sse += redS[(w * 128 + m) * 2 + 1];
        }
        float score = (se > 0.f) ? (sse / se) : 0.f;
        part = score * qmS[m];
        #pragma unroll
        for (int o = 16; o; o >>= 1) part += __shfl_xor_sync(0xFFFFFFFFu, part, o);
        if (lane == 0) red2[tid >> 5] = part;
    }
    __syncthreads();
    if (tid == 0) {
        float tot = red2[0] + red2[1] + red2[2] + red2[3];
        atomicAdd(&out[i * 32 + j], tot / g_qmsum[i]);
    }
}

// ---------------- launch ----------------
extern "C" void kernel_launch(void* const* d_in, const int* in_sizes, int n_in,
                              void* d_out, int out_size) {
    const float* q  = (const float*)d_in[0];
    const float* k  = (const float*)d_in[1];
    const float* qm = (const float*)d_in[2];
    const float* km = (const float*)d_in[3];
    const float* al = (const float*)d_in[4];
    const float* ls = (const float*)d_in[5];
    float* out = (float*)d_out;

    cudaFuncSetAttribute(li_main, cudaFuncAttributeMaxDynamicSharedMemorySize,
                         SMEM_BYTES);

    li_norm<<<2 * LI_BS, 256>>>(q, k);
    li_prep<<<LI_B, 256>>>(qm, out);
    li_main<<<dim3(64, 32), 512, SMEM_BYTES>>>(qm, km, al, ls, out);
}

// round 5
// speedup vs baseline: 2.4131x; 2.4131x over previous
#include <cuda_runtime.h>
#include <cuda_fp16.h>
#include <cstdint>
#include <cstddef>

// ---------------- problem constants ----------------
#define LI_B 32
#define LI_S 256
#define LI_H 768
#define LI_BS (LI_B * LI_S)   // 8192

#define NKC 12                 // 768 / 64
#define STG_A 32768            // A: 256 rows x 128 B
#define STG_B 36864            // B: 288 rows x 128 B (16 zero-pad rows each side)
#define STG_BYTES (STG_A + STG_B)   // 69632

// smem layout (dynamic)
#define OFF_DK   0             // 32 f32: scale * exp(-alpha*d)
#define OFF_KMP  128           // 288 f32: padded kmask indicator
#define OFF_QM   1280          // 256 f32
#define OFF_SH   2304          // 768 half: Ksum hi
#define OFF_SL   3840          // 768 half: Ksum lo
#define OFF_RED  5376          // 16 f32
#define OFF_STG  8192
#define SMEM_BYTES (OFF_STG + 3 * STG_BYTES)   // 217088

#define SWZ(c8, r) ((((c8) ^ ((r) & 7)) << 4))

// normalized fp16 copies of Q and K + small per-batch tables
__device__ __align__(128) __half g_qh[LI_BS * LI_H];
__device__ __align__(128) __half g_kh[LI_BS * LI_H];
__device__ float g_S[LI_B][LI_H];     // masked key sums (f32)
__device__ float g_qmsum[LI_B];
__device__ float g_nv[LI_B];

// ---------------- helpers ----------------
__device__ __forceinline__ uint32_t smem_u32(const void* p) {
    uint32_t a;
    asm("{ .reg .u64 t; cvta.to.shared.u64 t, %1; cvt.u32.u64 %0, t; }"
        : "=r"(a) : "l"(p));
    return a;
}

__device__ __forceinline__ void ldsm_x4(uint32_t& r0, uint32_t& r1,
                                        uint32_t& r2, uint32_t& r3, uint32_t addr) {
    asm volatile("ldmatrix.sync.aligned.m8n8.x4.shared.b16 {%0,%1,%2,%3}, [%4];"
                 : "=r"(r0), "=r"(r1), "=r"(r2), "=r"(r3) : "r"(addr));
}

__device__ __forceinline__ void mma16816(float& c0, float& c1, float& c2, float& c3,
                                         uint32_t a0, uint32_t a1, uint32_t a2, uint32_t a3,
                                         uint32_t b0, uint32_t b1) {
    asm volatile(
        "mma.sync.aligned.m16n8k16.row.col.f32.f16.f16.f32 "
        "{%0,%1,%2,%3}, {%4,%5,%6,%7}, {%8,%9}, {%0,%1,%2,%3};"
        : "+f"(c0), "+f"(c1), "+f"(c2), "+f"(c3)
        : "r"(a0), "r"(a1), "r"(a2), "r"(a3), "r"(b0), "r"(b1));
}

__device__ __forceinline__ void cpa16(uint32_t dst, const void* src) {
    asm volatile("cp.async.cg.shared.global [%0], [%1], 16;"
                 :: "r"(dst), "l"(__cvta_generic_to_global(src)));
}

// ---------------- kernel 1: normalize rows to fp16 (float4 path) ----------------
__global__ __launch_bounds__(192) void li_norm(const float* __restrict__ q,
                                               const float* __restrict__ k) {
    int row = blockIdx.x;
    bool isq = row < LI_BS;
    int r = isq ? row : row - LI_BS;
    const float4* src = (const float4*)((isq ? q : k) + (size_t)r * LI_H);
    __half2* dh = (__half2*)((isq ? g_qh : g_kh) + (size_t)r * LI_H);
    int t = threadIdx.x;

    float4 v = src[t];
    float ss = v.x * v.x + v.y * v.y + v.z * v.z + v.w * v.w;
    #pragma unroll
    for (int o = 16; o; o >>= 1) ss += __shfl_xor_sync(0xFFFFFFFFu, ss, o);

    __shared__ float red[6];
    if ((t & 31) == 0) red[t >> 5] = ss;
    __syncthreads();
    float tot = 0.f;
    #pragma unroll
    for (int w = 0; w < 6; w++) tot += red[w];
    float inv = 1.f / fmaxf(sqrtf(tot), 1e-12f);

    dh[2 * t]     = __floats2half2_rn(v.x * inv, v.y * inv);
    dh[2 * t + 1] = __floats2half2_rn(v.z * inv, v.w * inv);
}

// ---------------- kernel 2: qmask sums (clamped) + kmask valid counts ----------
__global__ __launch_bounds__(256) void li_prep(const float* __restrict__ qmask,
                                               const float* __restrict__ kmask) {
    int b = blockIdx.x, t = threadIdx.x;
    float v;
    if (b < 32) v = qmask[b * 256 + t];
    else        v = (kmask[(b - 32) * 256 + t] > 0.f) ? 1.f : 0.f;
    #pragma unroll
    for (int o = 16; o; o >>= 1) v += __shfl_xor_sync(0xFFFFFFFFu, v, o);
    __shared__ float red[8];
    if ((t & 31) == 0) red[t >> 5] = v;
    __syncthreads();
    if (t == 0) {
        float s = 0.f;
        #pragma unroll
        for (int w = 0; w < 8; w++) s += red[w];
        if (b < 32) g_qmsum[b] = fmaxf(s, 1.f);
        else        g_nv[b - 32] = s;
    }
}

// ---------------- kernel 3: masked key sums S_j[h] = sum_t 1[km>0] k[t][h] ----
__global__ __launch_bounds__(256) void li_ksum(const float* __restrict__ kmask) {
    int j = blockIdx.x, t = threadIdx.x;
    __shared__ float kmI[256];
    kmI[t] = (kmask[j * 256 + t] > 0.f) ? 1.f : 0.f;
    __syncthreads();
    const __half* kb = g_kh + (size_t)j * 256 * LI_H;
    float a0 = 0.f, a1 = 0.f, a2 = 0.f;
    for (int tt = 0; tt < 256; tt++) {
        if (kmI[tt] != 0.f) {
            const __half* rowp = kb + (size_t)tt * LI_H;
            a0 += __half2float(rowp[t]);
            a1 += __half2float(rowp[t + 256]);
            a2 += __half2float(rowp[t + 512]);
        }
    }
    g_S[j][t] = a0;
    g_S[j][t + 256] = a1;
    g_S[j][t + 512] = a2;
}

// ---------------- stage loader: A 256x64 + B 256x64 (rows offset +16) --------
__device__ __forceinline__ void load_stage(uint32_t stg, int kc, int qbase, int jbase,
                                           int tid) {
    int col0 = kc * 64;
    #pragma unroll
    for (int l = 0; l < 8; l++) {
        int idx = l * 512 + tid;
        if (idx < 2048) {
            int r = idx >> 3, c8 = idx & 7;
            cpa16(stg + r * 128 + SWZ(c8, r),
                  g_qh + (size_t)(qbase + r) * LI_H + col0 + c8 * 8);
        } else {
            int ib = idx - 2048;
            int r = ib >> 3, c8 = ib & 7;
            int pr = r + 16;
            cpa16(stg + STG_A + pr * 128 + SWZ(c8, pr),
                  g_kh + (size_t)(jbase + r) * LI_H + col0 + c8 * 8);
        }
    }
}

// ---------------- kernel 4: band GEMM + rank-1 base + decay-softmax ----------
__global__ __launch_bounds__(512, 1) void li_band(
    const float* __restrict__ qmask, const float* __restrict__ kmask,
    const float* __restrict__ p_alpha, const float* __restrict__ p_lscale,
    float* __restrict__ out) {
    extern __shared__ char smem[];
    const uint32_t sb = smem_u32(smem);
    const int tid = threadIdx.x, wid = tid >> 5, lane = tid & 31;
    const int i = blockIdx.x, j = blockIdx.y;
    const int qbase = i * 256, jbase = j * 256;

    float* dkS = (float*)(smem + OFF_DK);
    float* kmP = (float*)(smem + OFF_KMP);
    float* qmS = (float*)(smem + OFF_QM);
    __half2* Sh = (__half2*)(smem + OFF_SH);
    __half2* Sl = (__half2*)(smem + OFF_SL);
    float* redS = (float*)(smem + OFF_RED);

    // tables
    {
        float araw = p_alpha[0];
        float alpha = fmaxf(araw, 0.f) + log1pf(__expf(-fabsf(araw)));
        float scale = __expf(p_lscale[0]);
        if (tid < 32) dkS[tid] = scale * __expf(-alpha * (float)tid);
        if (tid < 288)
            kmP[tid] = (tid >= 16 && tid < 272)
                           ? ((kmask[jbase + tid - 16] > 0.f) ? 1.f : 0.f) : 0.f;
        if (tid < 256) qmS[tid] = qmask[qbase + tid];
        if (tid < 384) {
            float s0 = g_S[j][2 * tid], s1 = g_S[j][2 * tid + 1];
            __half h0 = __float2half_rn(s0), h1 = __float2half_rn(s1);
            Sh[tid] = __halves2half2(h0, h1);
            Sl[tid] = __floats2half2_rn(s0 - __half2float(h0), s1 - __half2float(h1));
        }
    }
    const uint32_t stg0 = sb + OFF_STG;
    // zero B pad rows (rows [0,16) and [272,288)) of all 3 stages
    for (int idx = tid; idx < 768; idx += 512) {
        int st = idx >> 8, rr = (idx & 255) >> 3, c = idx & 7;
        int pr = (rr < 16) ? rr : (256 + rr);
        uint32_t a = stg0 + st * STG_BYTES + STG_A + pr * 128 + c * 16;
        asm volatile("st.shared.v4.b32 [%0], {%1,%1,%1,%1};" :: "r"(a), "r"(0) : "memory");
    }

    // prologue
    #pragma unroll
    for (int s = 0; s < 3; s++) {
        load_stage(stg0 + s * STG_BYTES, s, qbase, jbase, tid);
        asm volatile("cp.async.commit_group;" ::: "memory");
    }

    float acc[6][4], accb[4];
    #pragma unroll
    for (int nt = 0; nt < 6; nt++)
        #pragma unroll
        for (int v = 0; v < 4; v++) acc[nt][v] = 0.f;
    #pragma unroll
    for (int v = 0; v < 4; v++) accb[v] = 0.f;

    // mainloop: warp wid owns s rows [16*wid, 16*wid+16), band t window 48 wide
    const int rA16 = 16 * wid + (lane & 15);
    for (int kc = 0; kc < NKC; kc++) {
        uint32_t stg = stg0 + (kc % 3) * STG_BYTES;
        asm volatile("cp.async.wait_group 2;" ::: "memory");
        __syncthreads();

        uint32_t sA = stg, sB = stg + STG_A;
        #pragma unroll
        for (int ks = 0; ks < 4; ks++) {
            int c8 = ks * 2 + (lane >> 4);
            uint32_t a0, a1, a2, a3;
            ldsm_x4(a0, a1, a2, a3, sA + rA16 * 128 + SWZ(c8, rA16));

            // pseudo-B: cols 0/1 = Ksum hi/lo  ->  rank-1 base term
            uint32_t pb0 = 0, pb1 = 0;
            if (lane < 8) {
                int kk2 = (kc * 64 + ks * 16) >> 1;
                int sub = lane & 3;
                __half2 v0 = (lane < 4 ? Sh : Sl)[kk2 + sub];
                __half2 v1 = (lane < 4 ? Sh : Sl)[kk2 + 4 + sub];
                pb0 = *(uint32_t*)&v0;
                pb1 = *(uint32_t*)&v1;
            }
            mma16816(accb[0], accb[1], accb[2], accb[3], a0, a1, a2, a3, pb0, pb1);

            #pragma unroll
            for (int p = 0; p < 3; p++) {
                int pr = 16 * wid + 16 * p + (lane & 15);
                uint32_t r0, r1, r2, r3;
                ldsm_x4(r0, r1, r2, r3, sB + pr * 128 + SWZ(c8, pr));
                mma16816(acc[2 * p][0], acc[2 * p][1], acc[2 * p][2], acc[2 * p][3],
                         a0, a1, a2, a3, r0, r2);
                mma16816(acc[2 * p + 1][0], acc[2 * p + 1][1],
                         acc[2 * p + 1][2], acc[2 * p + 1][3],
                         a0, a1, a2, a3, r1, r3);
            }
        }

        __syncthreads();
        if (kc + 3 < NKC) load_stage(stg, kc + 3, qbase, jbase, tid);
        asm volatile("cp.async.commit_group;" ::: "memory");
    }
    asm volatile("cp.async.wait_group 0;" ::: "memory");

    // ---------------- epilogue ----------------
    const int rA = 16 * wid + (lane >> 2);
    const int rB = rA + 8;
    float eA = 0.f, seA = 0.f, eB = 0.f, seB = 0.f;
    #pragma unroll
    for (int nt = 0; nt < 6; nt++) {
        int t0 = 16 * wid - 16 + nt * 8 + (lane & 3) * 2;
        #pragma unroll
        for (int v = 0; v < 2; v++) {
            int t = t0 + v;
            float km = kmP[t + 16];
            if (km > 0.f) {
                float sA_ = acc[nt][v], sB_ = acc[nt][2 + v];
                int dA = abs(rA - t), dB = abs(rB - t);
                float cA = __expf(sA_ * dkS[dA]) - 1.f;
                float cB = __expf(sB_ * dkS[dB]) - 1.f;
                eA += cA; seA += cA * sA_;
                eB += cB; seB += cB * sB_;
            }
        }
    }
    #pragma unroll
    for (int o = 1; o <= 2; o <<= 1) {
        eA  += __shfl_xor_sync(0xFFFFFFFFu, eA, o);
        seA += __shfl_xor_sync(0xFFFFFFFFu, seA, o);
        eB  += __shfl_xor_sync(0xFFFFFFFFu, eB, o);
        seB += __shfl_xor_sync(0xFFFFFFFFu, seB, o);
    }

    float val = 0.f;
    if ((lane & 3) == 0) {
        float NvJ = g_nv[j];
        float baseA = accb[0] + accb[1];   // cols 0(hi) + 1(lo)
        float baseB = accb[2] + accb[3];
        float suA = NvJ + eA, suB = NvJ + eB;
        float scA = (suA > 0.f) ? (baseA + seA) / suA : 0.f;
        float scB = (suB > 0.f) ? (baseB + seB) / suB : 0.f;
        val = scA * qmS[rA] + scB * qmS[rB];
    }
    #pragma unroll
    for (int o = 16; o; o >>= 1) val += __shfl_xor_sync(0xFFFFFFFFu, val, o);
    if (lane == 0) redS[wid] = val;
    __syncthreads();
    if (tid == 0) {
        float tot = 0.f;
        #pragma unroll
        for (int w = 0; w < 16; w++) tot += redS[w];
        out[i * 32 + j] = tot / g_qmsum[i];
    }
}

// ---------------- launch ----------------
extern "C" void kernel_launch(void* const* d_in, const int* in_sizes, int n_in,
                              void* d_out, int out_size) {
    const float* q  = (const float*)d_in[0];
    const float* k  = (const float*)d_in[1];
    const float* qm = (const float*)d_in[2];
    const float* km = (const float*)d_in[3];
    const float* al = (const float*)d_in[4];
    const float* ls = (const float*)d_in[5];
    float* out = (float*)d_out;

    cudaFuncSetAttribute(li_band, cudaFuncAttributeMaxDynamicSharedMemorySize,
                         SMEM_BYTES);

    li_norm<<<2 * LI_BS, 192>>>(q, k);
    li_prep<<<64, 256>>>(qm, km);
    li_ksum<<<32, 256>>>(km);
    li_band<<<dim3(LI_B, LI_B), 512, SMEM_BYTES>>>(qm, km, al, ls, out);
}

// round 9
// speedup vs baseline: 2.9069x; 1.2046x over previous
#include <cuda_runtime.h>
#include <cuda_fp16.h>
#include <cstdint>
#include <cstddef>

// ---------------- problem constants ----------------
#define LI_B 32
#define LI_S 256
#define LI_H 768
#define LI_BS (LI_B * LI_S)   // 8192

#define NKC 12                 // 768 / 64
// CTA: 128 s-rows x band W=8 window, 256 threads (8 warps of 16 rows)
#define STG_A 16384            // A: 128 rows x 128 B
#define STG_B 18432            // B: 144 rows x 128 B (8 pad rows at one end)
#define STG_BYTES (STG_A + STG_B)   // 34816

// smem layout (dynamic) -- NOTE: Sh/Sl are 1536 B EACH (768 half)
#define OFF_DK   0             // 32 f32
#define OFF_KMP  128           // 144 f32 (padded kmask indicator)
#define OFF_QM   768           // 128 f32
#define OFF_SH   1280          // 768 half: Ksum hi  [1280, 2816)
#define OFF_SL   2816          // 768 half: Ksum lo  [2816, 4352)
#define OFF_RED  4352          // 8 f32
#define OFF_STG  4608
#define SMEM_BYTES (OFF_STG + 3 * STG_BYTES)   // 109056

#define SWZ(c8, r) ((((c8) ^ ((r) & 7)) << 4))

// normalized fp16 copies of Q and K + small per-batch tables
__device__ __align__(128) __half g_qh[LI_BS * LI_H];
__device__ __align__(128) __half g_kh[LI_BS * LI_H];
__device__ float g_S[LI_B][LI_H];     // masked key sums (f32)
__device__ float g_qmsum[LI_B];
__device__ float g_nv[LI_B];

// ---------------- helpers ----------------
__device__ __forceinline__ uint32_t smem_u32(const void* p) {
    uint32_t a;
    asm("{ .reg .u64 t; cvta.to.shared.u64 t, %1; cvt.u32.u64 %0, t; }"
        : "=r"(a) : "l"(p));
    return a;
}

__device__ __forceinline__ void ldsm_x4(uint32_t& r0, uint32_t& r1,
                                        uint32_t& r2, uint32_t& r3, uint32_t addr) {
    asm volatile("ldmatrix.sync.aligned.m8n8.x4.shared.b16 {%0,%1,%2,%3}, [%4];"
                 : "=r"(r0), "=r"(r1), "=r"(r2), "=r"(r3) : "r"(addr));
}

__device__ __forceinline__ void mma16816(float& c0, float& c1, float& c2, float& c3,
                                         uint32_t a0, uint32_t a1, uint32_t a2, uint32_t a3,
                                         uint32_t b0, uint32_t b1) {
    asm volatile(
        "mma.sync.aligned.m16n8k16.row.col.f32.f16.f16.f32 "
        "{%0,%1,%2,%3}, {%4,%5,%6,%7}, {%8,%9}, {%0,%1,%2,%3};"
        : "+f"(c0), "+f"(c1), "+f"(c2), "+f"(c3)
        : "r"(a0), "r"(a1), "r"(a2), "r"(a3), "r"(b0), "r"(b1));
}

__device__ __forceinline__ void cpa16(uint32_t dst, const void* src) {
    asm volatile("cp.async.cg.shared.global [%0], [%1], 16;"
                 :: "r"(dst), "l"(__cvta_generic_to_global(src)));
}

// ---------------- kernel 1: normalize rows to fp16 ----------------
__global__ __launch_bounds__(192) void li_norm(const float* __restrict__ q,
                                               const float* __restrict__ k) {
    int row = blockIdx.x;
    bool isq = row < LI_BS;
    int r = isq ? row : row - LI_BS;
    const float4* src = (const float4*)((isq ? q : k) + (size_t)r * LI_H);
    __half2* dh = (__half2*)((isq ? g_qh : g_kh) + (size_t)r * LI_H);
    int t = threadIdx.x;

    float4 v = src[t];
    float ss = v.x * v.x + v.y * v.y + v.z * v.z + v.w * v.w;
    #pragma unroll
    for (int o = 16; o; o >>= 1) ss += __shfl_xor_sync(0xFFFFFFFFu, ss, o);

    __shared__ float red[6];
    if ((t & 31) == 0) red[t >> 5] = ss;
    __syncthreads();
    float tot = 0.f;
    #pragma unroll
    for (int w = 0; w < 6; w++) tot += red[w];
    float inv = 1.f / fmaxf(sqrtf(tot), 1e-12f);

    dh[2 * t]     = __floats2half2_rn(v.x * inv, v.y * inv);
    dh[2 * t + 1] = __floats2half2_rn(v.z * inv, v.w * inv);
}

// ---------------- kernel 2: qmask sums + kmask counts + zero out ------------
__global__ __launch_bounds__(256) void li_prep(const float* __restrict__ qmask,
                                               const float* __restrict__ kmask,
                                               float* __restrict__ out) {
    int b = blockIdx.x, t = threadIdx.x;
    float v;
    if (b < 32) v = qmask[b * 256 + t];
    else        v = (kmask[(b - 32) * 256 + t] > 0.f) ? 1.f : 0.f;
    #pragma unroll
    for (int o = 16; o; o >>= 1) v += __shfl_xor_sync(0xFFFFFFFFu, v, o);
    __shared__ float red[8];
    if ((t & 31) == 0) red[t >> 5] = v;
    __syncthreads();
    if (t == 0) {
        float s = 0.f;
        #pragma unroll
        for (int w = 0; w < 8; w++) s += red[w];
        if (b < 32) g_qmsum[b] = fmaxf(s, 1.f);
        else        g_nv[b - 32] = s;
    }
    if (b < 32 && t < 32) out[b * 32 + t] = 0.f;
}

// ---------------- kernel 3: masked key sums (grid 32 x 4) -------------------
__global__ __launch_bounds__(192) void li_ksum(const float* __restrict__ kmask) {
    int j = blockIdx.x, col = blockIdx.y * 192 + threadIdx.x;
    __shared__ float kmI[256];
    for (int t = threadIdx.x; t < 256; t += 192)
        kmI[t] = (kmask[j * 256 + t] > 0.f) ? 1.f : 0.f;
    __syncthreads();
    const __half* kb = g_kh + (size_t)j * 256 * LI_H;
    float a = 0.f;
    for (int tt = 0; tt < 256; tt++)
        if (kmI[tt] != 0.f) a += __half2float(kb[(size_t)tt * LI_H + col]);
    g_S[j][col] = a;
}

// ---------------- stage loader: A 128x64 + B 144x64 (band window) -----------
__device__ __forceinline__ void load_stage(uint32_t stg, int kc, int qrow0,
                                           int jbase, int mhalf, int tid) {
    int col0 = kc * 64;
    // A: 128 rows x 8 x 16B = 1024 ops
    #pragma unroll
    for (int l = 0; l < 4; l++) {
        int idx = l * 256 + tid;
        int r = idx >> 3, c8 = idx & 7;
        cpa16(stg + r * 128 + SWZ(c8, r),
              g_qh + (size_t)(qrow0 + r) * LI_H + col0 + c8 * 8);
    }
    // B: 144 rows x 8 = 1152 ops; row pr <-> key pos (mhalf*128 - 8 + pr)
    int tb0 = mhalf * 128 - 8;
    #pragma unroll
    for (int l = 0; l < 5; l++) {
        int idx = l * 256 + tid;
        if (idx < 1152) {
            int pr = idx >> 3, c8 = idx & 7;
            int krow = tb0 + pr;
            if (krow >= 0 && krow < 256)
                cpa16(stg + STG_A + pr * 128 + SWZ(c8, pr),
                      g_kh + (size_t)(jbase + krow) * LI_H + col0 + c8 * 8);
        }
    }
}

// ---------------- kernel 4: band GEMM + rank-1 base + decay-softmax ----------
__global__ __launch_bounds__(256, 2) void li_band(
    const float* __restrict__ qmask, const float* __restrict__ kmask,
    const float* __restrict__ p_alpha, const float* __restrict__ p_lscale,
    float* __restrict__ out) {
    extern __shared__ char smem[];
    const uint32_t sb = smem_u32(smem);
    const int tid = threadIdx.x, wid = tid >> 5, lane = tid & 31;
    const int i = blockIdx.x >> 1, mhalf = blockIdx.x & 1;
    const int j = blockIdx.y;
    const int jbase = j * 256;
    const int qrow0 = i * 256 + mhalf * 128;

    float* dkS = (float*)(smem + OFF_DK);
    float* kmP = (float*)(smem + OFF_KMP);
    float* qmS = (float*)(smem + OFF_QM);
    __half2* Sh = (__half2*)(smem + OFF_SH);
    __half2* Sl = (__half2*)(smem + OFF_SL);
    float* redS = (float*)(smem + OFF_RED);

    // tables
    {
        float araw = p_alpha[0];
        float alpha = fmaxf(araw, 0.f) + log1pf(__expf(-fabsf(araw)));
        float scale = __expf(p_lscale[0]);
        if (tid < 32) dkS[tid] = scale * __expf(-alpha * (float)tid);
        if (tid < 144) {
            int tpos = mhalf * 128 - 8 + tid;
            kmP[tid] = (tpos >= 0 && tpos < 256 && kmask[jbase + tpos] > 0.f)
                           ? 1.f : 0.f;
        }
        if (tid < 128) qmS[tid] = qmask[qrow0 + tid];
        #pragma unroll
        for (int idx = tid; idx < 384; idx += 256) {
            float s0 = g_S[j][2 * idx], s1 = g_S[j][2 * idx + 1];
            __half h0 = __float2half_rn(s0), h1 = __float2half_rn(s1);
            Sh[idx] = __halves2half2(h0, h1);
            Sl[idx] = __floats2half2_rn(s0 - __half2float(h0), s1 - __half2float(h1));
        }
    }
    const uint32_t stg0 = sb + OFF_STG;
    // zero B pad rows (8 rows at one end) in all 3 stages
    {
        int pad0 = (mhalf == 0) ? 0 : 136;
        if (tid < 192) {
            int st = tid / 64, rem = tid & 63;
            int pr = pad0 + (rem >> 3), c = rem & 7;
            uint32_t a = stg0 + st * STG_BYTES + STG_A + pr * 128 + c * 16;
            asm volatile("st.shared.v4.b32 [%0], {%1,%1,%1,%1};"
                         :: "r"(a), "r"(0) : "memory");
        }
    }

    // prologue
    #pragma unroll
    for (int s = 0; s < 3; s++) {
        load_stage(stg0 + s * STG_BYTES, s, qrow0, jbase, mhalf, tid);
        asm volatile("cp.async.commit_group;" ::: "memory");
    }

    float acc[4][4], accb[4];
    #pragma unroll
    for (int nt = 0; nt < 4; nt++)
        #pragma unroll
        for (int v = 0; v < 4; v++) acc[nt][v] = 0.f;
    #pragma unroll
    for (int v = 0; v < 4; v++) accb[v] = 0.f;

    // mainloop: warp wid owns local s rows [16*wid, +16), B window pr [16w, +32)
    const int rA16 = 16 * wid + (lane & 15);
    for (int kc = 0; kc < NKC; kc++) {
        uint32_t stg = stg0 + (kc % 3) * STG_BYTES;
        asm volatile("cp.async.wait_group 2;" ::: "memory");
        __syncthreads();

        uint32_t sA = stg, sB = stg + STG_A;
        #pragma unroll
        for (int ks = 0; ks < 4; ks++) {
            int c8 = ks * 2 + (lane >> 4);
            uint32_t a0, a1, a2, a3;
            ldsm_x4(a0, a1, a2, a3, sA + rA16 * 128 + SWZ(c8, rA16));

            // pseudo-B: cols 0/1 = Ksum hi/lo  ->  rank-1 base term
            uint32_t pb0 = 0, pb1 = 0;
            if (lane < 8) {
                int kk2 = (kc * 64 + ks * 16) >> 1;
                int sub = lane & 3;
                __half2 v0 = (lane < 4 ? Sh : Sl)[kk2 + sub];
                __half2 v1 = (lane < 4 ? Sh : Sl)[kk2 + 4 + sub];
                pb0 = *(uint32_t*)&v0;
                pb1 = *(uint32_t*)&v1;
            }
            mma16816(accb[0], accb[1], accb[2], accb[3], a0, a1, a2, a3, pb0, pb1);

            #pragma unroll
            for (int p = 0; p < 2; p++) {
                int pr = 16 * wid + 16 * p + (lane & 15);
                uint32_t r0, r1, r2, r3;
                ldsm_x4(r0, r1, r2, r3, sB + pr * 128 + SWZ(c8, pr));
                mma16816(acc[2 * p][0], acc[2 * p][1], acc[2 * p][2], acc[2 * p][3],
                         a0, a1, a2, a3, r0, r2);
                mma16816(acc[2 * p + 1][0], acc[2 * p + 1][1],
                         acc[2 * p + 1][2], acc[2 * p + 1][3],
                         a0, a1, a2, a3, r1, r3);
            }
        }

        __syncthreads();
        if (kc + 3 < NKC) load_stage(stg, kc + 3, qrow0, jbase, mhalf, tid);
        asm volatile("cp.async.commit_group;" ::: "memory");
    }
    asm volatile("cp.async.wait_group 0;" ::: "memory");

    // ---------------- epilogue ----------------
    const int lrow = lane >> 2;                 // 0..7
    float eA = 0.f, seA = 0.f, eB = 0.f, seB = 0.f;
    #pragma unroll
    for (int nt = 0; nt < 4; nt++) {
        int off0 = nt * 8 + (lane & 3) * 2;     // 0..31 within band window
        #pragma unroll
        for (int v = 0; v < 2; v++) {
            int off = off0 + v;
            float km = kmP[16 * wid + off];
            if (km > 0.f) {
                float sA_ = acc[nt][v], sB_ = acc[nt][2 + v];
                int dA = abs(lrow + 8 - off);
                int dB = abs(lrow + 16 - off);
                float cA = __expf(sA_ * dkS[dA]) - 1.f;
                float cB = __expf(sB_ * dkS[dB]) - 1.f;
                eA += cA; seA += cA * sA_;
                eB += cB; seB += cB * sB_;
            }
        }
    }
    #pragma unroll
    for (int o = 1; o <= 2; o <<= 1) {
        eA  += __shfl_xor_sync(0xFFFFFFFFu, eA, o);
        seA += __shfl_xor_sync(0xFFFFFFFFu, seA, o);
        eB  += __shfl_xor_sync(0xFFFFFFFFu, eB, o);
        seB += __shfl_xor_sync(0xFFFFFFFFu, seB, o);
    }

    float val = 0.f;
    if ((lane & 3) == 0) {
        float NvJ = g_nv[j];
        float baseA = accb[0] + accb[1];   // cols 0(hi) + 1(lo)
        float baseB = accb[2] + accb[3];
        float suA = NvJ + eA, suB = NvJ + eB;
        float scA = (suA > 0.f) ? (baseA + seA) / suA : 0.f;
        float scB = (suB > 0.f) ? (baseB + seB) / suB : 0.f;
        val = scA * qmS[16 * wid + lrow] + scB * qmS[16 * wid + lrow + 8];
    }
    #pragma unroll
    for (int o = 16; o; o >>= 1) val += __shfl_xor_sync(0xFFFFFFFFu, val, o);
    if (lane == 0) redS[wid] = val;
    __syncthreads();
    if (tid == 0) {
        float tot = 0.f;
        #pragma unroll
        for (int w = 0; w < 8; w++) tot += redS[w];
        atomicAdd(&out[i * 32 + j], tot / g_qmsum[i]);
    }
}

// ---------------- launch ----------------
extern "C" void kernel_launch(void* const* d_in, const int* in_sizes, int n_in,
                              void* d_out, int out_size) {
    const float* q  = (const float*)d_in[0];
    const float* k  = (const float*)d_in[1];
    const float* qm = (const float*)d_in[2];
    const float* km = (const float*)d_in[3];
    const float* al = (const float*)d_in[4];
    const float* ls = (const float*)d_in[5];
    float* out = (float*)d_out;

    cudaFuncSetAttribute(li_band, cudaFuncAttributeMaxDynamicSharedMemorySize,
                         SMEM_BYTES);

    li_norm<<<2 * LI_BS, 192>>>(q, k);
    li_prep<<<64, 256>>>(qm, km, out);
    li_ksum<<<dim3(32, 4), 192>>>(km);
    li_band<<<dim3(64, 32), 256, SMEM_BYTES>>>(qm, km, al, ls, out);
}

// round 14
// speedup vs baseline: 3.0619x; 1.0533x over previous
#include <cuda_runtime.h>
#include <cuda_fp16.h>
#include <cstdint>
#include <cstddef>

// ---------------- problem constants ----------------
#define LI_B 32
#define LI_S 256
#define LI_H 768
#define LI_BS (LI_B * LI_S)   // 8192

#define NKC 12                 // 768 / 64
// CTA: 128 s-rows x band W=8 window, 256 threads (8 warps of 16 rows)
#define STG_A 16384            // A: 128 rows x 128 B
#define STG_B 18432            // B: 144 rows x 128 B (8 pad rows at one end)
#define STG_BYTES (STG_A + STG_B)   // 34816

// smem layout (dynamic) -- Sh/Sl are 1536 B EACH (768 half)
#define OFF_DK   0             // 32 f32
#define OFF_KMP  128           // 144 f32 (padded kmask indicator)
#define OFF_QM   768           // 128 f32
#define OFF_SH   1280          // 768 half: Ksum hi  [1280, 2816)
#define OFF_SL   2816          // 768 half: Ksum lo  [2816, 4352)
#define OFF_RED  4352          // 8 f32
#define OFF_STG  4608
#define SMEM_BYTES (OFF_STG + 3 * STG_BYTES)   // 109056

#define SWZ(c8, r) ((((c8) ^ ((r) & 7)) << 4))

// normalized fp16 copies of Q and K + small per-batch tables
__device__ __align__(128) __half g_qh[LI_BS * LI_H];
__device__ __align__(128) __half g_kh[LI_BS * LI_H];
__device__ float g_S[LI_B][LI_H];     // masked key sums (f32)
__device__ float g_qmsum[LI_B];
__device__ float g_nv[LI_B];

// ---------------- helpers ----------------
__device__ __forceinline__ uint32_t smem_u32(const void* p) {
    uint32_t a;
    asm("{ .reg .u64 t; cvta.to.shared.u64 t, %1; cvt.u32.u64 %0, t; }"
        : "=r"(a) : "l"(p));
    return a;
}

__device__ __forceinline__ void ldsm_x4(uint32_t& r0, uint32_t& r1,
                                        uint32_t& r2, uint32_t& r3, uint32_t addr) {
    asm volatile("ldmatrix.sync.aligned.m8n8.x4.shared.b16 {%0,%1,%2,%3}, [%4];"
                 : "=r"(r0), "=r"(r1), "=r"(r2), "=r"(r3) : "r"(addr));
}

__device__ __forceinline__ void mma16816(float& c0, float& c1, float& c2, float& c3,
                                         uint32_t a0, uint32_t a1, uint32_t a2, uint32_t a3,
                                         uint32_t b0, uint32_t b1) {
    asm volatile(
        "mma.sync.aligned.m16n8k16.row.col.f32.f16.f16.f32 "
        "{%0,%1,%2,%3}, {%4,%5,%6,%7}, {%8,%9}, {%0,%1,%2,%3};"
        : "+f"(c0), "+f"(c1), "+f"(c2), "+f"(c3)
        : "r"(a0), "r"(a1), "r"(a2), "r"(a3), "r"(b0), "r"(b1));
}

__device__ __forceinline__ void cpa16(uint32_t dst, const void* src) {
    asm volatile("cp.async.cg.shared.global [%0], [%1], 16;"
                 :: "r"(dst), "l"(__cvta_generic_to_global(src)));
}

// ---------------- kernel 1: normalize rows to fp16 (warp per row) -----------
__global__ __launch_bounds__(256) void li_norm(const float* __restrict__ q,
                                               const float* __restrict__ k) {
    int wid = threadIdx.x >> 5, lane = threadIdx.x & 31;
    int row = blockIdx.x * 8 + wid;       // grid 2048 -> 16384 rows
    bool isq = row < LI_BS;
    int r = isq ? row : row - LI_BS;
    const float4* src = (const float4*)((isq ? q : k) + (size_t)r * LI_H);
    uint2* dst = (uint2*)((isq ? g_qh : g_kh) + (size_t)r * LI_H);

    float4 v[6];
    float ss = 0.f;
    #pragma unroll
    for (int it = 0; it < 6; it++) {
        v[it] = src[lane + 32 * it];
        ss += v[it].x * v[it].x + v[it].y * v[it].y
            + v[it].z * v[it].z + v[it].w * v[it].w;
    }
    #pragma unroll
    for (int o = 16; o; o >>= 1) ss += __shfl_xor_sync(0xFFFFFFFFu, ss, o);
    float inv = 1.f / fmaxf(sqrtf(ss), 1e-12f);

    #pragma unroll
    for (int it = 0; it < 6; it++) {
        __half2 h0 = __floats2half2_rn(v[it].x * inv, v[it].y * inv);
        __half2 h1 = __floats2half2_rn(v[it].z * inv, v[it].w * inv);
        uint2 o2;
        o2.x = *(uint32_t*)&h0;
        o2.y = *(uint32_t*)&h1;
        dst[lane + 32 * it] = o2;
    }
}

// ---------------- kernel 2: qmask sums + kmask counts + zero out ------------
__global__ __launch_bounds__(256) void li_prep(const float* __restrict__ qmask,
                                               const float* __restrict__ kmask,
                                               float* __restrict__ out) {
    int b = blockIdx.x, t = threadIdx.x;
    float v;
    if (b < 32) v = qmask[b * 256 + t];
    else        v = (kmask[(b - 32) * 256 + t] > 0.f) ? 1.f : 0.f;
    #pragma unroll
    for (int o = 16; o; o >>= 1) v += __shfl_xor_sync(0xFFFFFFFFu, v, o);
    __shared__ float red[8];
    if ((t & 31) == 0) red[t >> 5] = v;
    __syncthreads();
    if (t == 0) {
        float s = 0.f;
        #pragma unroll
        for (int w = 0; w < 8; w++) s += red[w];
        if (b < 32) g_qmsum[b] = fmaxf(s, 1.f);
        else        g_nv[b - 32] = s;
    }
    if (b < 32 && t < 32) out[b * 32 + t] = 0.f;
}

// ---------------- kernel 3: masked key sums (grid 32 x 4) -------------------
__global__ __launch_bounds__(192) void li_ksum(const float* __restrict__ kmask) {
    int j = blockIdx.x, col = blockIdx.y * 192 + threadIdx.x;
    __shared__ float kmI[256];
    for (int t = threadIdx.x; t < 256; t += 192)
        kmI[t] = (kmask[j * 256 + t] > 0.f) ? 1.f : 0.f;
    __syncthreads();
    const __half* kb = g_kh + (size_t)j * 256 * LI_H;
    float a = 0.f;
    for (int tt = 0; tt < 256; tt++)
        if (kmI[tt] != 0.f) a += __half2float(kb[(size_t)tt * LI_H + col]);
    g_S[j][col] = a;
}

// ---------------- kernel 4: band GEMM + rank-1 base + decay-softmax ----------
__global__ __launch_bounds__(256, 2) void li_band(
    const float* __restrict__ qmask, const float* __restrict__ kmask,
    const float* __restrict__ p_alpha, const float* __restrict__ p_lscale,
    float* __restrict__ out) {
    extern __shared__ char smem[];
    const uint32_t sb = smem_u32(smem);
    const int tid = threadIdx.x, wid = tid >> 5, lane = tid & 31;
    const int i = blockIdx.x >> 1, mhalf = blockIdx.x & 1;
    const int j = blockIdx.y;
    const int jbase = j * 256;
    const int qrow0 = i * 256 + mhalf * 128;

    float* dkS = (float*)(smem + OFF_DK);
    float* kmP = (float*)(smem + OFF_KMP);
    float* qmS = (float*)(smem + OFF_QM);
    __half2* Sh = (__half2*)(smem + OFF_SH);
    __half2* Sl = (__half2*)(smem + OFF_SL);
    float* redS = (float*)(smem + OFF_RED);

    const int tb0 = mhalf * 128 - 8;

    // tables
    {
        float araw = p_alpha[0];
        float alpha = fmaxf(araw, 0.f) + log1pf(__expf(-fabsf(araw)));
        float scale = __expf(p_lscale[0]);
        if (tid < 32) dkS[tid] = scale * __expf(-alpha * (float)tid);
        if (tid < 144) {
            int tpos = tb0 + tid;
            kmP[tid] = (tpos >= 0 && tpos < 256 && kmask[jbase + tpos] > 0.f)
                           ? 1.f : 0.f;
        }
        if (tid < 128) qmS[tid] = qmask[qrow0 + tid];
        #pragma unroll
        for (int idx = tid; idx < 384; idx += 256) {
            float s0 = g_S[j][2 * idx], s1 = g_S[j][2 * idx + 1];
            __half h0 = __float2half_rn(s0), h1 = __float2half_rn(s1);
            Sh[idx] = __halves2half2(h0, h1);
            Sl[idx] = __floats2half2_rn(s0 - __half2float(h0), s1 - __half2float(h1));
        }
    }
    const uint32_t stg0 = sb + OFF_STG;
    // zero B pad rows (8 rows at one end) in all 3 stages
    {
        int pad0 = (mhalf == 0) ? 0 : 136;
        if (tid < 192) {
            int st = tid / 64, rem = tid & 63;
            int pr = pad0 + (rem >> 3), c = rem & 7;
            uint32_t a = stg0 + st * STG_BYTES + STG_A + pr * 128 + c * 16;
            asm volatile("st.shared.v4.b32 [%0], {%1,%1,%1,%1};"
                         :: "r"(a), "r"(0) : "memory");
        }
    }

    // -------- precomputed load pointers (chunk-invariant except +128B/chunk)
    const int r0 = tid >> 3, c8t = tid & 7;
    const char* gA = (const char*)(g_qh + (size_t)(qrow0 + r0) * LI_H + c8t * 8);
    const char* gB = (const char*)(g_kh + ((size_t)(jbase + tb0 + r0) * LI_H
                                           + c8t * 8) * 1);   // may be OOB; predicated
    const uint32_t swc = ((uint32_t)(c8t ^ (r0 & 7))) << 4;
    const uint32_t dA0 = (uint32_t)(r0 * 128) + swc;
    const uint32_t dB0 = STG_A + (uint32_t)(r0 * 128) + swc;
    uint32_t vm = 0;
    #pragma unroll
    for (int l = 0; l < 5; l++) {
        int krow = tb0 + 32 * l + r0;
        bool v = (krow >= 0) && (krow < 256) && (l < 4 || tid < 128);
        vm |= (v ? 1u : 0u) << l;
    }

    // -------- precomputed ldsm address components
    const int l15 = lane & 15, hi = lane >> 4, l7 = lane & 7;
    const uint32_t cA  = (uint32_t)((16 * wid + l15) * 128);
    const uint32_t cB0 = STG_A + cA;
    const uint32_t cB1 = cB0 + 2048;
    uint32_t off[4];
    #pragma unroll
    for (int ks = 0; ks < 4; ks++) off[ks] = (uint32_t)(((2 * ks + hi) ^ l7) << 4);

    // prologue: stages 0..2
    #pragma unroll
    for (int s = 0; s < 3; s++) {
        uint32_t stg = stg0 + s * STG_BYTES;
        #pragma unroll
        for (int l = 0; l < 4; l++)
            cpa16(stg + dA0 + 4096 * l, gA + 49152 * l);
        #pragma unroll
        for (int l = 0; l < 5; l++)
            if (vm & (1u << l)) cpa16(stg + dB0 + 4096 * l, gB + 49152 * l);
        gA += 128; gB += 128;
        asm volatile("cp.async.commit_group;" ::: "memory");
    }

    float acc[4][4], accb[4];
    #pragma unroll
    for (int nt = 0; nt < 4; nt++)
        #pragma unroll
        for (int v = 0; v < 4; v++) acc[nt][v] = 0.f;
    #pragma unroll
    for (int v = 0; v < 4; v++) accb[v] = 0.f;

    // mainloop: 4 outer iterations x 3 unrolled buffers
    for (int ko = 0; ko < 4; ko++) {
        #pragma unroll
        for (int u = 0; u < 3; u++) {
            const uint32_t stg = stg0 + u * STG_BYTES;
            const int kc = ko * 3 + u;
            asm volatile("cp.async.wait_group 2;" ::: "memory");
            __syncthreads();

            // prefetch rank-1 pseudo-B fragments for all 4 ks (independent of ring)
            uint32_t pb0[4], pb1[4];
            #pragma unroll
            for (int ks = 0; ks < 4; ks++) {
                pb0[ks] = 0; pb1[ks] = 0;
                if (lane < 8) {
                    int kk2 = kc * 32 + 8 * ks;
                    int sub = lane & 3;
                    __half2 v0 = (lane < 4 ? Sh : Sl)[kk2 + sub];
                    __half2 v1 = (lane < 4 ? Sh : Sl)[kk2 + 4 + sub];
                    pb0[ks] = *(uint32_t*)&v0;
                    pb1[ks] = *(uint32_t*)&v1;
                }
            }

            #pragma unroll
            for (int ks = 0; ks < 4; ks++) {
                uint32_t a0, a1, a2, a3;
                ldsm_x4(a0, a1, a2, a3, stg + cA + off[ks]);
                mma16816(accb[0], accb[1], accb[2], accb[3],
                         a0, a1, a2, a3, pb0[ks], pb1[ks]);
                uint32_t r0_, r1_, r2_, r3_;
                ldsm_x4(r0_, r1_, r2_, r3_, stg + cB0 + off[ks]);
                mma16816(acc[0][0], acc[0][1], acc[0][2], acc[0][3],
                         a0, a1, a2, a3, r0_, r2_);
                mma16816(acc[1][0], acc[1][1], acc[1][2], acc[1][3],
                         a0, a1, a2, a3, r1_, r3_);
                ldsm_x4(r0_, r1_, r2_, r3_, stg + cB1 + off[ks]);
                mma16816(acc[2][0], acc[2][1], acc[2][2], acc[2][3],
                         a0, a1, a2, a3, r0_, r2_);
                mma16816(acc[3][0], acc[3][1], acc[3][2], acc[3][3],
                         a0, a1, a2, a3, r1_, r3_);
            }

            __syncthreads();
            if (ko < 3) {
                #pragma unroll
                for (int l = 0; l < 4; l++)
                    cpa16(stg + dA0 + 4096 * l, gA + 49152 * l);
                #pragma unroll
                for (int l = 0; l < 5; l++)
                    if (vm & (1u << l)) cpa16(stg + dB0 + 4096 * l, gB + 49152 * l);
                gA += 128; gB += 128;
            }
            asm volatile("cp.async.commit_group;" ::: "memory");
        }
    }
    asm volatile("cp.async.wait_group 0;" ::: "memory");

    // ---------------- epilogue ----------------
    const int lrow = lane >> 2;                 // 0..7
    float eA = 0.f, seA = 0.f, eB = 0.f, seB = 0.f;
    #pragma unroll
    for (int nt = 0; nt < 4; nt++) {
        int off0 = nt * 8 + (lane & 3) * 2;     // 0..31 within band window
        #pragma unroll
        for (int v = 0; v < 2; v++) {
            int offc = off0 + v;
            float km = kmP[16 * wid + offc];
            if (km > 0.f) {
                float sA_ = acc[nt][v], sB_ = acc[nt][2 + v];
                int dA = abs(lrow + 8 - offc);
                int dB = abs(lrow + 16 - offc);
                float cA_ = __expf(sA_ * dkS[dA]) - 1.f;
                float cB_ = __expf(sB_ * dkS[dB]) - 1.f;
                eA += cA_; seA += cA_ * sA_;
                eB += cB_; seB += cB_ * sB_;
            }
        }
    }
    #pragma unroll
    for (int o = 1; o <= 2; o <<= 1) {
        eA  += __shfl_xor_sync(0xFFFFFFFFu, eA, o);
        seA += __shfl_xor_sync(0xFFFFFFFFu, seA, o);
        eB  += __shfl_xor_sync(0xFFFFFFFFu, eB, o);
        seB += __shfl_xor_sync(0xFFFFFFFFu, seB, o);
    }

    float val = 0.f;
    if ((lane & 3) == 0) {
        float NvJ = g_nv[j];
        float baseA = accb[0] + accb[1];   // cols 0(hi) + 1(lo)
        float baseB = accb[2] + accb[3];
        float suA = NvJ + eA, suB = NvJ + eB;
        float scA = (suA > 0.f) ? (baseA + seA) / suA : 0.f;
        float scB = (suB > 0.f) ? (baseB + seB) / suB : 0.f;
        val = scA * qmS[16 * wid + lrow] + scB * qmS[16 * wid + lrow + 8];
    }
    #pragma unroll
    for (int o = 16; o; o >>= 1) val += __shfl_xor_sync(0xFFFFFFFFu, val, o);
    if (lane == 0) redS[wid] = val;
    __syncthreads();
    if (tid == 0) {
        float tot = 0.f;
        #pragma unroll
        for (int w = 0; w < 8; w++) tot += redS[w];
        atomicAdd(&out[i * 32 + j], tot / g_qmsum[i]);
    }
}

// ---------------- launch ----------------
extern "C" void kernel_launch(void* const* d_in, const int* in_sizes, int n_in,
                              void* d_out, int out_size) {
    const float* q  = (const float*)d_in[0];
    const float* k  = (const float*)d_in[1];
    const float* qm = (const float*)d_in[2];
    const float* km = (const float*)d_in[3];
    const float* al = (const float*)d_in[4];
    const float* ls = (const float*)d_in[5];
    float* out = (float*)d_out;

    cudaFuncSetAttribute(li_band, cudaFuncAttributeMaxDynamicSharedMemorySize,
                         SMEM_BYTES);

    li_norm<<<2048, 256>>>(q, k);
    li_prep<<<64, 256>>>(qm, km, out);
    li_ksum<<<dim3(32, 4), 192>>>(km);
    li_band<<<dim3(64, 32), 256, SMEM_BYTES>>>(qm, km, al, ls, out);
}